// round 16
// baseline (speedup 1.0000x reference)
#include <cuda_runtime.h>
#include <cuda_bf16.h>
#include <cstdint>
#include <cstddef>

// Problem constants
#define BB 2
#define CC 256
#define HH 64
#define WW 64
#define PP 4096          // H*W
#define NSET 128
#define GG 64            // groups
#define CGC 4            // channels per group

// ---------------- scratch (device globals; no allocs allowed) ----------------
__device__ float g_mean[BB * CC];
__device__ float g_sca[BB * CC];
__device__ float g_ydw1[BB * CC * PP];
__device__ float g_yc1a[BB * CC * PP];
__device__ float g_attlin[BB * NSET * PP];
__device__ float g_x1[BB * CC * PP];
__device__ float g_uf[BB * CC * PP];
__device__ float g_l1[BB * CC * PP];
__device__ float g_tg[BB * 16 * PP];
__device__ uint32_t g_attpk[BB * 64 * PP];        // att packed bf16x2 [b][kp][pix]
__device__ uint32_t g_wpk[6144 * 64];             // wcb packed bf16x2 [col][kp]
__device__ uint32_t g_wghi[1152 * 128];           // 1x1 weights hi [row][kp]
__device__ uint32_t g_wglo[1152 * 128];           // 1x1 weights lo [row][kp]
__device__ float g_x2[BB * CC * PP];
__device__ float g_z[BB * CC * PP];

#define MMA_BF16(ACC, A, B0, B1)                                              \
    asm volatile(                                                             \
        "mma.sync.aligned.m16n8k16.row.col.f32.bf16.bf16.f32 "                \
        "{%0,%1,%2,%3}, {%4,%5,%6,%7}, {%8,%9}, {%0,%1,%2,%3};"               \
        : "+f"((ACC)[0]), "+f"((ACC)[1]), "+f"((ACC)[2]), "+f"((ACC)[3])      \
        : "r"((A)[0]), "r"((A)[1]), "r"((A)[2]), "r"((A)[3]),                 \
          "r"(B0), "r"(B1))

__device__ __forceinline__ uint32_t pack_bf16(float a, float b,
                                              float& ra, float& rb) {
    __nv_bfloat162 h = __floats2bfloat162_rn(a, b);
    ra = a - __bfloat162float(h.x);
    rb = b - __bfloat162float(h.y);
    return *(uint32_t*)&h;
}
__device__ __forceinline__ uint32_t pack_bf16n(float a, float b) {
    __nv_bfloat162 h = __floats2bfloat162_rn(a, b);
    return *(uint32_t*)&h;
}

// ---------------- mean over H,W per (b,c) ----------------
__global__ void __launch_bounds__(256) meankern(const float* __restrict__ X,
                                                float* __restrict__ M) {
    int bc = blockIdx.x;
    const float4* xp = (const float4*)(X + (size_t)bc * PP);
    float s = 0.f;
    for (int p = threadIdx.x; p < PP / 4; p += 256) {
        float4 v = xp[p];
        s += v.x + v.y + v.z + v.w;
    }
    __shared__ float red[256];
    red[threadIdx.x] = s;
    __syncthreads();
    for (int st = 128; st > 0; st >>= 1) {
        if (threadIdx.x < st) red[threadIdx.x] += red[threadIdx.x + st];
        __syncthreads();
    }
    if (threadIdx.x == 0) M[bc] = red[0] * (1.f / PP);
}

// ---------------- sca = 1x1 conv on the mean vector ----------------
__global__ void __launch_bounds__(256) scakern(const float* __restrict__ M,
                                               const float* __restrict__ Wsca,
                                               const float* __restrict__ Bsca,
                                               float* __restrict__ SCA) {
    int b = blockIdx.x;
    int o = threadIdx.x;
    __shared__ float m[CC];
    m[o] = M[b * CC + o];
    __syncthreads();
    float s = Bsca[o];
    const float* wr = Wsca + (size_t)o * CC;
    for (int c = 0; c < CC; c++) s += wr[c] * m[c];
    SCA[b * CC + o] = s;
}

// ---------------- wcb -> packed bf16 pairs [col][kp] ----------------
__global__ void __launch_bounds__(256) wcb_pack(const float* __restrict__ wcb,
                                                uint32_t* __restrict__ wpk) {
    int c = blockIdx.x * 256 + threadIdx.x;    // 0..6143
    uint32_t* dst = wpk + (size_t)c * 64;
#pragma unroll 8
    for (int kp = 0; kp < 64; kp++)
        dst[kp] = pack_bf16n(wcb[(size_t)(2 * kp) * 6144 + c],
                             wcb[(size_t)(2 * kp + 1) * 6144 + c]);
}

// ---------------- 1x1 weights -> bf16 hi/lo [row][kp] ----------------
// rows: 0 dw1 | 256 c1a | 512 c211 | 640 lka1 | 896 proj
__global__ void __launch_bounds__(128) wpack(const float* __restrict__ dw1,
                                             const float* __restrict__ c1a,
                                             const float* __restrict__ c211,
                                             const float* __restrict__ lka1,
                                             const float* __restrict__ proj,
                                             uint32_t* __restrict__ hi,
                                             uint32_t* __restrict__ lo) {
    int row = blockIdx.x;
    const float* src;
    if (row < 256)      src = dw1 + (size_t)row * 256;
    else if (row < 512) src = c1a + (size_t)(row - 256) * 256;
    else if (row < 640) src = c211 + (size_t)(row - 512) * 256;
    else if (row < 896) src = lka1 + (size_t)(row - 640) * 256;
    else                src = proj + (size_t)(row - 896) * 256;
    int kp = threadIdx.x;
    float a = src[2 * kp], b = src[2 * kp + 1], ra, rb;
    hi[(size_t)row * 128 + kp] = pack_bf16(a, b, ra, rb);
    lo[(size_t)row * 128 + kp] = pack_bf16n(ra, rb);
}

// =========================================================================
// bf16x3 1x1-conv GEMM, prepacked weights + register-prefetch pipeline.
// Tile 64M x 128N, mma m16n8k16, 8 warps (2m x 4n).
// MODE 0: 3-way batch | MODE 1: lka merge epilogue | MODE 2: plain
// =========================================================================
#define GB_A_ST 20
#define GB_B_ST 136
#define GT_SMEM_FLOATS (2 * 1280 + 2 * 2176)   // 6912 floats = 27.6 KB

template <int MODE>
__global__ void __launch_bounds__(256) gemm_tc(
    const uint32_t* __restrict__ WHI, const uint32_t* __restrict__ WLO,
    const float* __restrict__ bias2,
    const float* __restrict__ X,
    float* __restrict__ Y0, float* __restrict__ Y1, float* __restrict__ Y2,
    const float* __restrict__ EX1, const float* __restrict__ EX2,
    const float* __restrict__ SCA) {
    extern __shared__ float smraw[];
    uint32_t* Ahi = (uint32_t*)smraw;              // [64][20]
    uint32_t* Alo = Ahi + 1280;
    uint32_t* Bhi = Alo + 1280;                    // [16][136]
    uint32_t* Blo = Bhi + 2176;

    int b = blockIdx.z, n0 = blockIdx.x << 7, my = blockIdx.y;
    float* Y;
    const float* bias = nullptr;
    int m0, Msel, rb;
    if (MODE == 0) {
        if (my < 4)      { rb = 0;   Y = Y0; m0 = my << 6; Msel = 256; }
        else if (my < 8) { rb = 256; Y = Y1; m0 = (my - 4) << 6; Msel = 256; }
        else             { rb = 512; Y = Y2; m0 = (my - 8) << 6; Msel = 128; bias = bias2; }
    } else if (MODE == 1) {
        rb = 640; Y = Y0; m0 = my << 6; Msel = 256; bias = bias2;
    } else {
        rb = 896; Y = Y0; m0 = my << 6; Msel = 256;
    }
    const float* Xb = X + (size_t)b * 256 * PP;
    int tid = threadIdx.x;
    int am = tid >> 2, at = tid & 3;
    int warp = tid >> 5, lane = tid & 31;
    int wm = warp & 1, wn = warp >> 1;
    int qr = lane >> 2, l4 = lane & 3;
    int m_warp = wm << 5, n_warp = wn << 5;
    float acc[2][4][4] = {};

    const uint32_t* wRowHi = WHI + (size_t)(rb + m0 + am) * 128 + at * 4;
    const uint32_t* wRowLo = WLO + (size_t)(rb + m0 + am) * 128 + at * 4;

    uint4 pAh, pAl;
    float4 pva[2], pvb[2];
    // ---- prefetch chunk 0
    pAh = *(const uint4*)&wRowHi[0];
    pAl = *(const uint4*)&wRowLo[0];
#pragma unroll
    for (int j = 0; j < 2; j++) {
        int idx = tid + (j << 8);
        int kp = idx >> 5, nq = idx & 31;
        const float* xr = &Xb[(size_t)(kp * 2) * PP + n0 + (nq << 2)];
        pva[j] = *(const float4*)xr;
        pvb[j] = *(const float4*)(xr + PP);
    }

    for (int k0 = 0; k0 < 256; k0 += 32) {
        // ---- STS phase from prefetch regs
        {
            int base = am * GB_A_ST + at * 4;
            *(uint4*)&Ahi[base] = pAh;
            *(uint4*)&Alo[base] = pAl;
        }
#pragma unroll
        for (int j = 0; j < 2; j++) {
            int idx = tid + (j << 8);
            int kp = idx >> 5, nq = idx & 31;
            float r0, r1, r2, r3, r4, r5, r6, r7;
            uint4 h, l;
            h.x = pack_bf16(pva[j].x, pvb[j].x, r0, r1);
            h.y = pack_bf16(pva[j].y, pvb[j].y, r2, r3);
            h.z = pack_bf16(pva[j].z, pvb[j].z, r4, r5);
            h.w = pack_bf16(pva[j].w, pvb[j].w, r6, r7);
            l.x = pack_bf16n(r0, r1);
            l.y = pack_bf16n(r2, r3);
            l.z = pack_bf16n(r4, r5);
            l.w = pack_bf16n(r6, r7);
            int base = kp * GB_B_ST + (nq << 2);
            *(uint4*)&Bhi[base] = h;
            *(uint4*)&Blo[base] = l;
        }
        __syncthreads();

        // ---- prefetch next chunk (overlaps with mma below)
        if (k0 + 32 < 256) {
            int kn = k0 + 32;
            pAh = *(const uint4*)&wRowHi[kn >> 1];
            pAl = *(const uint4*)&wRowLo[kn >> 1];
#pragma unroll
            for (int j = 0; j < 2; j++) {
                int idx = tid + (j << 8);
                int kp = idx >> 5, nq = idx & 31;
                const float* xr = &Xb[(size_t)(kn + kp * 2) * PP + n0 + (nq << 2)];
                pva[j] = *(const float4*)xr;
                pvb[j] = *(const float4*)(xr + PP);
            }
        }

#pragma unroll
        for (int ks = 0; ks < 2; ks++) {
            uint32_t ah[2][4], al[2][4];
#pragma unroll
            for (int mt = 0; mt < 2; mt++) {
                int r0 = (m_warp + mt * 16 + qr) * GB_A_ST + ks * 8 + l4;
                int r1 = r0 + 8 * GB_A_ST;
                ah[mt][0] = Ahi[r0];     ah[mt][1] = Ahi[r1];
                ah[mt][2] = Ahi[r0 + 4]; ah[mt][3] = Ahi[r1 + 4];
                al[mt][0] = Alo[r0];     al[mt][1] = Alo[r1];
                al[mt][2] = Alo[r0 + 4]; al[mt][3] = Alo[r1 + 4];
            }
#pragma unroll
            for (int nt = 0; nt < 4; nt++) {
                int ncol = n_warp + nt * 8 + qr;
                int kb0 = (ks * 8 + l4) * GB_B_ST + ncol;
                int kb1 = kb0 + 4 * GB_B_ST;
                uint32_t bh0 = Bhi[kb0], bh1 = Bhi[kb1];
                uint32_t bl0 = Blo[kb0], bl1 = Blo[kb1];
#pragma unroll
                for (int mt = 0; mt < 2; mt++) {
                    MMA_BF16(acc[mt][nt], ah[mt], bh0, bh1);
                    MMA_BF16(acc[mt][nt], ah[mt], bl0, bl1);
                    MMA_BF16(acc[mt][nt], al[mt], bh0, bh1);
                }
            }
        }
        __syncthreads();
    }

    float* Yb = Y + (size_t)b * Msel * PP;
#pragma unroll
    for (int mt = 0; mt < 2; mt++)
#pragma unroll
        for (int nt = 0; nt < 4; nt++) {
            int row = m_warp + mt * 16 + qr;
            int col = n_warp + nt * 8 + (l4 << 1);
#pragma unroll
            for (int rr = 0; rr < 2; rr++) {
                int rm = m0 + row + rr * 8;
                float c0 = acc[mt][nt][rr * 2], c1 = acc[mt][nt][rr * 2 + 1];
                size_t yidx = (size_t)(row + rr * 8 + m0) * PP + n0 + col;
                if (MODE == 1) {
                    float bb = bias[rm];
                    float sc = SCA[b * CC + rm];
                    size_t gidx = (size_t)b * CC * PP + (size_t)rm * PP + n0 + col;
                    float2 v1 = *(const float2*)&EX1[gidx];
                    float2 v2 = *(const float2*)&EX2[gidx];
                    float2 o = make_float2((c0 + bb) * v1.x * v2.x * sc,
                                           (c1 + bb) * v1.y * v2.y * sc);
                    *(float2*)&Yb[yidx] = o;
                } else {
                    float bb = (MODE == 0 && bias) ? bias[rm] : 0.f;
                    *(float2*)&Yb[yidx] = make_float2(c0 + bb, c1 + bb);
                }
            }
        }
}

// ---------------- depthwise conv body (predicated, small taps) ----------
template <int KS, int DIL, int PAD>
__device__ __forceinline__ void dw_conv_tile(const float* __restrict__ tile,
                                             const float* __restrict__ w,
                                             float* gout) {
    for (int p = threadIdx.x; p < PP; p += 256) {
        int h = p >> 6, ww = p & 63;
        float s = 0.f;
#pragma unroll
        for (int kh = 0; kh < KS; kh++) {
            int hh = h + DIL * kh - PAD;
            if ((unsigned)hh >= (unsigned)HH) continue;
#pragma unroll
            for (int kw = 0; kw < KS; kw++) {
                int wc = ww + DIL * kw - PAD;
                if ((unsigned)wc >= (unsigned)WW) continue;
                s += tile[hh * WW + wc] * w[kh * KS + kw];
            }
        }
        gout[p] = s;
    }
}

// two independent 3x3 depthwise convs in one launch (unpadded, proven)
__global__ void __launch_bounds__(256) dw3x3_pair(const float* __restrict__ X0,
                                                  const float* __restrict__ W0,
                                                  float* __restrict__ Y0,
                                                  const float* __restrict__ X1,
                                                  const float* __restrict__ W1,
                                                  float* __restrict__ Y1) {
    __shared__ float tile[PP];
    __shared__ float w[9];
    int id = blockIdx.x;
    int which = id >> 9, bc = id & 511;
    int c = bc & (CC - 1);
    const float* X = which ? X1 : X0;
    const float* Wd = which ? W1 : W0;
    float* Y = which ? Y1 : Y0;
    const float4* xp = (const float4*)(X + (size_t)bc * PP);
    for (int p = threadIdx.x; p < PP / 4; p += 256)
        ((float4*)tile)[p] = xp[p];
    if (threadIdx.x < 9) w[threadIdx.x] = Wd[c * 9 + threadIdx.x];
    __syncthreads();
    dw_conv_tile<3, 1, 1>(tile, w, Y + (size_t)bc * PP);
}

// fused LKA depthwise chain with padded tiles (proven)
__global__ void __launch_bounds__(256) lka_chain(const float* __restrict__ X,
                                                 const float* __restrict__ W5,
                                                 const float* __restrict__ W7,
                                                 float* __restrict__ OUT) {
    __shared__ float t0p[68 * 68];
    __shared__ float t1p[82 * 84];
    __shared__ float w5[25], w7[49];
    int bc = blockIdx.x;
    int c = bc & (CC - 1);
    for (int i = threadIdx.x; i < (68 * 68) / 4; i += 256)
        ((float4*)t0p)[i] = make_float4(0.f, 0.f, 0.f, 0.f);
    for (int i = threadIdx.x; i < (82 * 84) / 4; i += 256)
        ((float4*)t1p)[i] = make_float4(0.f, 0.f, 0.f, 0.f);
    if (threadIdx.x < 25) w5[threadIdx.x] = W5[c * 25 + threadIdx.x];
    else if (threadIdx.x >= 32 && threadIdx.x < 81)
        w7[threadIdx.x - 32] = W7[c * 49 + threadIdx.x - 32];
    __syncthreads();
    const float* xp = X + (size_t)bc * PP;
    for (int p = threadIdx.x; p < PP; p += 256) {
        int h = p >> 6, ww = p & 63;
        t0p[(h + 2) * 68 + ww + 2] = xp[p];
    }
    __syncthreads();
    for (int p = threadIdx.x; p < PP; p += 256) {
        int h = p >> 6, ww = p & 63;
        const float* base = &t0p[h * 68 + ww];
        float s = 0.f;
#pragma unroll
        for (int kh = 0; kh < 5; kh++)
#pragma unroll
            for (int kw = 0; kw < 5; kw++)
                s += base[kh * 68 + kw] * w5[kh * 5 + kw];
        t1p[(h + 9) * 84 + ww + 9] = s;
    }
    __syncthreads();
    float* yp = OUT + (size_t)bc * PP;
    for (int p = threadIdx.x; p < PP; p += 256) {
        int h = p >> 6, ww = p & 63;
        const float* base = &t1p[h * 84 + ww];
        float s = 0.f;
#pragma unroll
        for (int kh = 0; kh < 7; kh++)
#pragma unroll
            for (int kw = 0; kw < 7; kw++)
                s += base[kh * 3 * 84 + kw * 3] * w7[kh * 7 + kw];
        yp[p] = s;
    }
}

// ---------------- c2a grouped conv (groups=32) + SimpleGate ----------------
__global__ void __launch_bounds__(256) c2a_gate(const float* __restrict__ X,
                                                const float* __restrict__ Wg,
                                                const float* __restrict__ bg,
                                                float* __restrict__ TG) {
    int b = blockIdx.x >> 4, j = blockIdx.x & 15;
    int p0 = blockIdx.y * 512;
    __shared__ float w1[72], w2[72];
    if (threadIdx.x < 72) w1[threadIdx.x] = Wg[j * 72 + threadIdx.x];
    else if (threadIdx.x < 144) w2[threadIdx.x - 72] = Wg[(16 + j) * 72 + threadIdx.x - 72];
    __syncthreads();
    float b1 = bg[j], b2 = bg[16 + j];
    const float* x1p = X + ((size_t)b * CC + j * 8) * PP;
    const float* x2p = X + ((size_t)b * CC + (16 + j) * 8) * PP;
    for (int p = p0 + threadIdx.x; p < p0 + 512; p += 256) {
        int h = p >> 6, wq = p & 63;
        float t1 = b1, t2 = b2;
        for (int ci = 0; ci < 8; ci++) {
#pragma unroll
            for (int kh = 0; kh < 3; kh++) {
                int hh = h + kh - 1;
                if ((unsigned)hh >= (unsigned)HH) continue;
#pragma unroll
                for (int kw = 0; kw < 3; kw++) {
                    int wc = wq + kw - 1;
                    if ((unsigned)wc >= (unsigned)WW) continue;
                    float xv1 = x1p[(size_t)ci * PP + hh * WW + wc];
                    float xv2 = x2p[(size_t)ci * PP + hh * WW + wc];
                    t1 += xv1 * w1[ci * 9 + kh * 3 + kw];
                    t2 += xv2 * w2[ci * 9 + kh * 3 + kw];
                }
            }
        }
        TG[((size_t)b * 16 + j) * PP + p] = t1 * t2;
    }
}

// ---------------- att pair -> packed bf16x2 [b][kp][pix] ----------------
__global__ void __launch_bounds__(256) att_mix_pk(const float* __restrict__ TG,
                                                  const float* __restrict__ c2bw,
                                                  const float* __restrict__ c2bb,
                                                  const float* __restrict__ attg,
                                                  const float* __restrict__ ATTLIN,
                                                  uint32_t* __restrict__ APK) {
    int kp = blockIdx.x;                 // 0..63
    int b = blockIdx.z;
    int p0 = blockIdx.y * 1024;
    int n0 = 2 * kp, n1 = n0 + 1;
    float wr0[16], wr1[16];
#pragma unroll
    for (int q = 0; q < 16; q++) {
        wr0[q] = c2bw[n0 * 16 + q];
        wr1[q] = c2bw[n1 * 16 + q];
    }
    float bb0 = c2bb[n0], gam0 = attg[n0];
    float bb1 = c2bb[n1], gam1 = attg[n1];
    const float* tgb = TG + (size_t)b * 16 * PP;
    const float* al0 = ATTLIN + ((size_t)b * NSET + n0) * PP;
    const float* al1 = ATTLIN + ((size_t)b * NSET + n1) * PP;
    uint32_t* dst = APK + ((size_t)b * 64 + kp) * PP;
    for (int p = p0 + threadIdx.x; p < p0 + 1024; p += 256) {
        float s0 = bb0, s1 = bb1;
#pragma unroll
        for (int q = 0; q < 16; q++) {
            float t = tgb[(size_t)q * PP + p];
            s0 += t * wr0[q];
            s1 += t * wr1[q];
        }
        dst[p] = pack_bf16n(s0 * gam0 + al0[p], s1 * gam1 + al1[p]);
    }
}

// =========================================================================
// Dual-pass IKBA, bf16 k16 mma, prepacked operands (R15-proven).
// =========================================================================
#define A_ST 136
#define BKP_ST 36
#define IK_BV (32 * A_ST)                  // 4352
#define IK_BH (IK_BV + 56 * BKP_ST)        // 6368
#define IKBA_SMEM_FLOATS 15104

__global__ void __launch_bounds__(128, 3) ikba_dual(
        const uint32_t* __restrict__ APK, const uint32_t* __restrict__ WPK,
        const float* __restrict__ bcb, const float* __restrict__ ga1,
        const float* __restrict__ UF, float* __restrict__ OUT) {
    extern __shared__ float sm[];
    uint32_t* Ap = (uint32_t*)sm;              // [32 kp][A_ST]
    uint32_t* BV = (uint32_t*)(sm + IK_BV);    // [56 n][BKP_ST]
    uint32_t* BH = (uint32_t*)(sm + IK_BH);    // [56 n][BKP_ST]
    float* CsV = sm;                           // alias: [128][57]
    float* CsH = sm + 7296;                    // alias: [128][57]
    float* xh = sm + 14592;                    // alias: [4][128]

    int gr = blockIdx.x, h2 = blockIdx.y, b = blockIdx.z;
    int tid = threadIdx.x;
    int warp = tid >> 5, lane = tid & 31;
    int qr = lane >> 2, l4 = lane & 3;
    int m_base = warp << 5;

    float accV[2][7][4], accH[2][7][4];
#pragma unroll
    for (int i = 0; i < 2; i++)
#pragma unroll
        for (int j = 0; j < 7; j++)
#pragma unroll
            for (int t = 0; t < 4; t++) { accV[i][j][t] = 0.f; accH[i][j][t] = 0.f; }

#pragma unroll
    for (int kc = 0; kc < 2; kc++) {
        {
            int quad = tid & 31, klane = tid >> 5;
            const uint32_t* apk = APK + ((size_t)b * 64 + kc * 32) * PP
                                + (size_t)h2 * 128 + quad * 4;
#pragma unroll
            for (int kk = 0; kk < 32; kk += 4) {
                int kp = kk + klane;
                *(uint4*)&Ap[kp * A_ST + quad * 4] =
                    *(const uint4*)&apk[(size_t)kp * PP];
            }
        }
        {
            const uint32_t* wv = WPK + (size_t)(gr * 48) * 64 + kc * 32;
            const uint32_t* wh = WPK + (size_t)(3072 + gr * 48) * 64 + kc * 32;
#pragma unroll
            for (int j = 0; j < 3; j++) {
                int l = j * 128 + tid;
                int n = l >> 3, q = l & 7;
                *(uint4*)&BV[n * BKP_ST + q * 4] =
                    *(const uint4*)&wv[(size_t)n * 64 + q * 4];
                *(uint4*)&BH[n * BKP_ST + q * 4] =
                    *(const uint4*)&wh[(size_t)n * 64 + q * 4];
            }
        }
        int kbase = kc * 64;
#pragma unroll
        for (int j = 0; j < 2; j++) {
            int l = j * 128 + tid;
            int kp = l >> 3, n = 48 + (l & 7);
            BV[n * BKP_ST + kp] = 0u;
            float v0 = 0.f, v1 = 0.f;
            if (n < 52) {
                v0 = bcb[(kbase + 2 * kp) * CC + gr * CGC + (n - 48)];
                v1 = bcb[(kbase + 2 * kp + 1) * CC + gr * CGC + (n - 48)];
            }
            BH[n * BKP_ST + kp] = pack_bf16n(v0, v1);
        }
        __syncthreads();

        for (int kq = 0; kq < 32; kq += 8) {
            uint32_t a[2][4];
            int ka = (kq + l4) * A_ST;
            int ka2 = (kq + 4 + l4) * A_ST;
#pragma unroll
            for (int mt = 0; mt < 2; mt++) {
                int row = m_base + mt * 16 + qr;
                a[mt][0] = Ap[ka + row];
                a[mt][1] = Ap[ka + row + 8];
                a[mt][2] = Ap[ka2 + row];
                a[mt][3] = Ap[ka2 + row + 8];
            }
#pragma unroll
            for (int nt = 0; nt < 7; nt++) {
                int nr = (nt * 8 + qr) * BKP_ST + kq + l4;
                uint32_t bv0 = BV[nr], bv1 = BV[nr + 4];
                uint32_t bh0 = BH[nr], bh1 = BH[nr + 4];
#pragma unroll
                for (int mt = 0; mt < 2; mt++) {
                    MMA_BF16(accV[mt][nt], a[mt], bv0, bv1);
                    MMA_BF16(accH[mt][nt], a[mt], bh0, bh1);
                }
            }
        }
        __syncthreads();
    }

#pragma unroll
    for (int mt = 0; mt < 2; mt++)
#pragma unroll
        for (int nt = 0; nt < 7; nt++) {
            int r = m_base + mt * 16 + qr;
            int cl = nt * 8 + 2 * l4;
            CsV[r * 57 + cl]           = accV[mt][nt][0];
            CsV[r * 57 + cl + 1]       = accV[mt][nt][1];
            CsV[(r + 8) * 57 + cl]     = accV[mt][nt][2];
            CsV[(r + 8) * 57 + cl + 1] = accV[mt][nt][3];
            CsH[r * 57 + cl]           = accH[mt][nt][0];
            CsH[r * 57 + cl + 1]       = accH[mt][nt][1];
            CsH[(r + 8) * 57 + cl]     = accH[mt][nt][2];
            CsH[(r + 8) * 57 + cl + 1] = accH[mt][nt][3];
        }
    __syncthreads();

    int pix = tid, r0 = pix >> 6, cp = pix & 63;
    int h = h2 * 2 + r0;
    {
        float uf[12];
        size_t srcBase = (size_t)(b * CC + gr * CGC) * PP;
#pragma unroll
        for (int ci = 0; ci < 4; ci++)
#pragma unroll
            for (int tap = 0; tap < 3; tap++) {
                float v = 0.f;
                int hh = h + tap - 1;
                if ((unsigned)hh < (unsigned)HH)
                    v = UF[srcBase + (size_t)ci * PP + hh * WW + cp];
                uf[ci * 3 + tap] = v;
            }
        const float* cpr = &CsV[pix * 57];
#pragma unroll
        for (int oi = 0; oi < 4; oi++) {
            float s = 0.f;
#pragma unroll
            for (int j = 0; j < 12; j++) s += cpr[oi * 12 + j] * uf[j];
            xh[oi * 128 + pix] = s;
        }
    }
    __syncthreads();

    {
        float ufh[12];
#pragma unroll
        for (int ci = 0; ci < 4; ci++)
#pragma unroll
            for (int tap = 0; tap < 3; tap++) {
                float v = 0.f;
                int wc = cp + tap - 1;
                if ((unsigned)wc < (unsigned)WW)
                    v = xh[ci * 128 + pix + tap - 1];
                ufh[ci * 3 + tap] = v;
            }
        const float* cpr = &CsH[pix * 57];
        size_t obase = (size_t)(b * CC + gr * CGC) * PP + (size_t)h2 * 128 + pix;
#pragma unroll
        for (int oi = 0; oi < 4; oi++) {
            float s = cpr[48 + oi];
#pragma unroll
            for (int j = 0; j < 12; j++) s += cpr[oi * 12 + j] * ufh[j];
            size_t oidx = obase + (size_t)oi * PP;
            OUT[oidx] = s * ga1[gr * CGC + oi] + UF[oidx];
        }
    }
}

// ---------------- launch ----------------
extern "C" void kernel_launch(void* const* d_in, const int* in_sizes, int n_in,
                              void* d_out, int out_size) {
    const float* x       = (const float*)d_in[0];
    const float* dw1_w   = (const float*)d_in[1];
    const float* dw2_w   = (const float*)d_in[2];
    const float* proj_w  = (const float*)d_in[3];
    const float* lka0_w  = (const float*)d_in[4];
    const float* lkas_w  = (const float*)d_in[5];
    const float* lka1_w  = (const float*)d_in[6];
    const float* lka1_b  = (const float*)d_in[7];
    const float* sca_w   = (const float*)d_in[8];
    const float* sca_b   = (const float*)d_in[9];
    const float* c1a_w   = (const float*)d_in[10];
    const float* c1b_w   = (const float*)d_in[11];
    const float* c2a_w   = (const float*)d_in[12];
    const float* c2a_b   = (const float*)d_in[13];
    const float* c2b_w   = (const float*)d_in[14];
    const float* c2b_b   = (const float*)d_in[15];
    const float* c211_w  = (const float*)d_in[16];
    const float* c211_b  = (const float*)d_in[17];
    const float* w_cb    = (const float*)d_in[18];
    const float* b_cb    = (const float*)d_in[19];
    const float* attgam  = (const float*)d_in[20];
    const float* ga1     = (const float*)d_in[21];
    float* out = (float*)d_out;

    float *meanb, *scab, *ydw1, *yc1a, *attlin, *x1b, *ufb, *l1,
          *tg, *x2b, *zb;
    uint32_t *attpk, *wpk, *wghi, *wglo;
    cudaGetSymbolAddress((void**)&meanb, g_mean);
    cudaGetSymbolAddress((void**)&scab, g_sca);
    cudaGetSymbolAddress((void**)&ydw1, g_ydw1);
    cudaGetSymbolAddress((void**)&yc1a, g_yc1a);
    cudaGetSymbolAddress((void**)&attlin, g_attlin);
    cudaGetSymbolAddress((void**)&x1b, g_x1);
    cudaGetSymbolAddress((void**)&ufb, g_uf);
    cudaGetSymbolAddress((void**)&l1, g_l1);
    cudaGetSymbolAddress((void**)&tg, g_tg);
    cudaGetSymbolAddress((void**)&attpk, g_attpk);
    cudaGetSymbolAddress((void**)&wpk, g_wpk);
    cudaGetSymbolAddress((void**)&wghi, g_wghi);
    cudaGetSymbolAddress((void**)&wglo, g_wglo);
    cudaGetSymbolAddress((void**)&x2b, g_x2);
    cudaGetSymbolAddress((void**)&zb, g_z);

    size_t gt_smem = GT_SMEM_FLOATS * sizeof(float);

    // prep: pack wcb + 1x1 weights to bf16
    wcb_pack<<<24, 256>>>(w_cb, wpk);
    wpack<<<1152, 128>>>(dw1_w, c1a_w, c211_w, lka1_w, proj_w, wghi, wglo);

    // channel-attention branch
    meankern<<<BB * CC, 256>>>(x, meanb);
    scakern<<<BB, 256>>>(meanb, sca_w, sca_b, scab);

    // 1x1 convs from x, batched (dw1 -> ydw1, c1a -> yc1a, c211 -> attlin)
    gemm_tc<0><<<dim3(32, 10, BB), 256, gt_smem>>>(
        wghi, wglo, c211_b, x, ydw1, yc1a, attlin,
        nullptr, nullptr, nullptr);

    // depthwise: two 3x3 merged (unpadded); LKA chain (padded tiles)
    dw3x3_pair<<<BB * CC * 2, 256>>>(ydw1, dw2_w, x1b, yc1a, c1b_w, ufb);
    lka_chain<<<BB * CC, 256>>>(x, lka0_w, lkas_w, l1);

    // attention map -> packed bf16
    c2a_gate<<<dim3(BB * 16, 8), 256>>>(x, c2a_w, c2a_b, tg);
    att_mix_pk<<<dim3(64, 4, BB), 256>>>(tg, c2b_w, c2b_b, attgam, attlin, attpk);

    // dual-pass IKBA (bf16 k16 mma, prepacked fills)
    size_t shmem = IKBA_SMEM_FLOATS * sizeof(float);
    cudaFuncSetAttribute(ikba_dual, cudaFuncAttributeMaxDynamicSharedMemorySize,
                         (int)shmem);
    ikba_dual<<<dim3(GG, 32, BB), 128, shmem>>>(attpk, wpk, b_cb, ga1, ufb, x2b);

    // lka1 GEMM with fused elementwise merge: z = (W@l1+b)*x1*x2*sca
    gemm_tc<1><<<dim3(32, 4, BB), 256, gt_smem>>>(
        wghi, wglo, lka1_b, l1, zb, nullptr, nullptr,
        x1b, x2b, scab);

    // final projection
    gemm_tc<2><<<dim3(32, 4, BB), 256, gt_smem>>>(
        wghi, wglo, nullptr, zb, out, nullptr, nullptr,
        nullptr, nullptr, nullptr);
}

// round 17
// speedup vs baseline: 1.1687x; 1.1687x over previous
#include <cuda_runtime.h>
#include <cuda_bf16.h>
#include <cstdint>
#include <cstddef>

// Problem constants
#define BB 2
#define CC 256
#define HH 64
#define WW 64
#define PP 4096          // H*W
#define NSET 128
#define GG 64            // groups
#define CGC 4            // channels per group

// ---------------- scratch (device globals; no allocs allowed) ----------------
__device__ float g_mean[BB * CC];
__device__ float g_sca[BB * CC];
__device__ float g_ydw1[BB * CC * PP];
__device__ float g_yc1a[BB * CC * PP];
__device__ float g_attlin[BB * NSET * PP];
__device__ float g_x1[BB * CC * PP];
__device__ float g_uf[BB * CC * PP];
__device__ float g_l1[BB * CC * PP];
__device__ float g_tg[BB * 16 * PP];
__device__ uint32_t g_attpk[BB * 64 * PP];        // att packed bf16x2 [b][kp][pix]
__device__ uint32_t g_wpk[6144 * 64];             // wcb packed bf16x2 [col][kp]
__device__ float g_x2[BB * CC * PP];
__device__ float g_z[BB * CC * PP];

#define MMA_BF16(ACC, A, B0, B1)                                              \
    asm volatile(                                                             \
        "mma.sync.aligned.m16n8k16.row.col.f32.bf16.bf16.f32 "                \
        "{%0,%1,%2,%3}, {%4,%5,%6,%7}, {%8,%9}, {%0,%1,%2,%3};"               \
        : "+f"((ACC)[0]), "+f"((ACC)[1]), "+f"((ACC)[2]), "+f"((ACC)[3])      \
        : "r"((A)[0]), "r"((A)[1]), "r"((A)[2]), "r"((A)[3]),                 \
          "r"(B0), "r"(B1))

__device__ __forceinline__ uint32_t pack_bf16(float a, float b,
                                              float& ra, float& rb) {
    __nv_bfloat162 h = __floats2bfloat162_rn(a, b);
    ra = a - __bfloat162float(h.x);
    rb = b - __bfloat162float(h.y);
    return *(uint32_t*)&h;
}
__device__ __forceinline__ uint32_t pack_bf16n(float a, float b) {
    __nv_bfloat162 h = __floats2bfloat162_rn(a, b);
    return *(uint32_t*)&h;
}

// ---------------- mean over H,W per (b,c) ----------------
__global__ void __launch_bounds__(256) meankern(const float* __restrict__ X,
                                                float* __restrict__ M) {
    int bc = blockIdx.x;
    const float4* xp = (const float4*)(X + (size_t)bc * PP);
    float s = 0.f;
    for (int p = threadIdx.x; p < PP / 4; p += 256) {
        float4 v = xp[p];
        s += v.x + v.y + v.z + v.w;
    }
    __shared__ float red[256];
    red[threadIdx.x] = s;
    __syncthreads();
    for (int st = 128; st > 0; st >>= 1) {
        if (threadIdx.x < st) red[threadIdx.x] += red[threadIdx.x + st];
        __syncthreads();
    }
    if (threadIdx.x == 0) M[bc] = red[0] * (1.f / PP);
}

// ---------------- sca: warp-per-output 1x1 conv on the mean vector -------
// 64 blocks x 8 warps; warp w of block blk computes output o = blk*8 + w.
__global__ void __launch_bounds__(256) scakern(const float* __restrict__ M,
                                               const float* __restrict__ Wsca,
                                               const float* __restrict__ Bsca,
                                               float* __restrict__ SCA) {
    __shared__ float m[CC];
    int o = blockIdx.x * 8 + (threadIdx.x >> 5);   // 0..511
    int b = o >> 8, oc = o & 255;
    int lane = threadIdx.x & 31;
    // all outputs in this block share b (8 divides 256)
    for (int c = threadIdx.x; c < CC; c += 256) m[c] = M[b * CC + c];
    __syncthreads();
    const float* wr = Wsca + (size_t)oc * CC;
    float s = 0.f;
#pragma unroll
    for (int i = 0; i < 8; i++) {
        int c = lane + i * 32;
        s += wr[c] * m[c];
    }
#pragma unroll
    for (int st = 16; st > 0; st >>= 1)
        s += __shfl_xor_sync(0xFFFFFFFF, s, st);
    if (lane == 0) SCA[o] = s + Bsca[oc];
}

// ---------------- wcb -> packed bf16 pairs [col][kp] ----------------
__global__ void __launch_bounds__(256) wcb_pack(const float* __restrict__ wcb,
                                                uint32_t* __restrict__ wpk) {
    int c = blockIdx.x * 256 + threadIdx.x;    // 0..6143
    uint32_t* dst = wpk + (size_t)c * 64;
#pragma unroll 8
    for (int kp = 0; kp < 64; kp++)
        dst[kp] = pack_bf16n(wcb[(size_t)(2 * kp) * 6144 + c],
                             wcb[(size_t)(2 * kp + 1) * 6144 + c]);
}

// =========================================================================
// bf16x3 1x1-conv GEMM (R15-proven). Tile 64M x 128N, mma m16n8k16.
// MODE 0: 3-way batch | MODE 1: lka merge epilogue | MODE 2: plain
// =========================================================================
#define GB_A_ST 20
#define GB_B_ST 136
#define GT_SMEM_FLOATS (2 * 1280 + 2 * 2176)   // 6912 floats = 27.6 KB

template <int MODE>
__global__ void __launch_bounds__(256) gemm_tc(
    const float* __restrict__ W0, const float* __restrict__ W1,
    const float* __restrict__ W2, const float* __restrict__ bias2,
    const float* __restrict__ X,
    float* __restrict__ Y0, float* __restrict__ Y1, float* __restrict__ Y2,
    const float* __restrict__ EX1, const float* __restrict__ EX2,
    const float* __restrict__ SCA) {
    extern __shared__ float smraw[];
    uint32_t* Ahi = (uint32_t*)smraw;              // [64][20]
    uint32_t* Alo = Ahi + 1280;
    uint32_t* Bhi = Alo + 1280;                    // [16][136]
    uint32_t* Blo = Bhi + 2176;

    int b = blockIdx.z, n0 = blockIdx.x << 7, my = blockIdx.y;
    const float* W;
    float* Y;
    const float* bias = nullptr;
    int m0, Msel;
    if (MODE == 0) {
        if (my < 4)      { W = W0; Y = Y0; m0 = my << 6; Msel = 256; }
        else if (my < 8) { W = W1; Y = Y1; m0 = (my - 4) << 6; Msel = 256; }
        else             { W = W2; Y = Y2; m0 = (my - 8) << 6; Msel = 128; bias = bias2; }
    } else {
        W = W0; Y = Y0; m0 = my << 6; Msel = 256; bias = bias2;
    }
    const float* Xb = X + (size_t)b * 256 * PP;
    int tid = threadIdx.x;
    int am = tid >> 2, at = tid & 3;
    int warp = tid >> 5, lane = tid & 31;
    int wm = warp & 1, wn = warp >> 1;
    int qr = lane >> 2, l4 = lane & 3;
    int m_warp = wm << 5, n_warp = wn << 5;
    float acc[2][4][4] = {};

    for (int k0 = 0; k0 < 256; k0 += 32) {
        {
            const float* wr = &W[(size_t)(m0 + am) * 256 + k0 + at * 8];
            float4 v0 = *(const float4*)wr;
            float4 v1 = *(const float4*)(wr + 4);
            float r0, r1, r2, r3, r4, r5, r6, r7;
            uint4 h, l;
            h.x = pack_bf16(v0.x, v0.y, r0, r1);
            h.y = pack_bf16(v0.z, v0.w, r2, r3);
            h.z = pack_bf16(v1.x, v1.y, r4, r5);
            h.w = pack_bf16(v1.z, v1.w, r6, r7);
            l.x = pack_bf16n(r0, r1);
            l.y = pack_bf16n(r2, r3);
            l.z = pack_bf16n(r4, r5);
            l.w = pack_bf16n(r6, r7);
            int base = am * GB_A_ST + at * 4;
            *(uint4*)&Ahi[base] = h;
            *(uint4*)&Alo[base] = l;
        }
#pragma unroll
        for (int j = 0; j < 2; j++) {
            int idx = tid + (j << 8);
            int kp = idx >> 5, nq = idx & 31;
            const float* xr = &Xb[(size_t)(k0 + kp * 2) * PP + n0 + (nq << 2)];
            float4 va = *(const float4*)xr;
            float4 vb = *(const float4*)(xr + PP);
            float r0, r1, r2, r3, r4, r5, r6, r7;
            uint4 h, l;
            h.x = pack_bf16(va.x, vb.x, r0, r1);
            h.y = pack_bf16(va.y, vb.y, r2, r3);
            h.z = pack_bf16(va.z, vb.z, r4, r5);
            h.w = pack_bf16(va.w, vb.w, r6, r7);
            l.x = pack_bf16n(r0, r1);
            l.y = pack_bf16n(r2, r3);
            l.z = pack_bf16n(r4, r5);
            l.w = pack_bf16n(r6, r7);
            int base = kp * GB_B_ST + (nq << 2);
            *(uint4*)&Bhi[base] = h;
            *(uint4*)&Blo[base] = l;
        }
        __syncthreads();

#pragma unroll
        for (int ks = 0; ks < 2; ks++) {
            uint32_t ah[2][4], al[2][4];
#pragma unroll
            for (int mt = 0; mt < 2; mt++) {
                int r0 = (m_warp + mt * 16 + qr) * GB_A_ST + ks * 8 + l4;
                int r1 = r0 + 8 * GB_A_ST;
                ah[mt][0] = Ahi[r0];     ah[mt][1] = Ahi[r1];
                ah[mt][2] = Ahi[r0 + 4]; ah[mt][3] = Ahi[r1 + 4];
                al[mt][0] = Alo[r0];     al[mt][1] = Alo[r1];
                al[mt][2] = Alo[r0 + 4]; al[mt][3] = Alo[r1 + 4];
            }
#pragma unroll
            for (int nt = 0; nt < 4; nt++) {
                int ncol = n_warp + nt * 8 + qr;
                int kb0 = (ks * 8 + l4) * GB_B_ST + ncol;
                int kb1 = kb0 + 4 * GB_B_ST;
                uint32_t bh0 = Bhi[kb0], bh1 = Bhi[kb1];
                uint32_t bl0 = Blo[kb0], bl1 = Blo[kb1];
#pragma unroll
                for (int mt = 0; mt < 2; mt++) {
                    MMA_BF16(acc[mt][nt], ah[mt], bh0, bh1);
                    MMA_BF16(acc[mt][nt], ah[mt], bl0, bl1);
                    MMA_BF16(acc[mt][nt], al[mt], bh0, bh1);
                }
            }
        }
        __syncthreads();
    }

    float* Yb = Y + (size_t)b * Msel * PP;
#pragma unroll
    for (int mt = 0; mt < 2; mt++)
#pragma unroll
        for (int nt = 0; nt < 4; nt++) {
            int row = m_warp + mt * 16 + qr;
            int col = n_warp + nt * 8 + (l4 << 1);
#pragma unroll
            for (int rr = 0; rr < 2; rr++) {
                int rm = m0 + row + rr * 8;
                float c0 = acc[mt][nt][rr * 2], c1 = acc[mt][nt][rr * 2 + 1];
                size_t yidx = (size_t)(row + rr * 8 + m0) * PP + n0 + col;
                if (MODE == 1) {
                    float bb = bias[rm];
                    float sc = SCA[b * CC + rm];
                    size_t gidx = (size_t)b * CC * PP + (size_t)rm * PP + n0 + col;
                    float2 v1 = *(const float2*)&EX1[gidx];
                    float2 v2 = *(const float2*)&EX2[gidx];
                    float2 o = make_float2((c0 + bb) * v1.x * v2.x * sc,
                                           (c1 + bb) * v1.y * v2.y * sc);
                    *(float2*)&Yb[yidx] = o;
                } else {
                    float bb = (MODE == 0 && bias) ? bias[rm] : 0.f;
                    *(float2*)&Yb[yidx] = make_float2(c0 + bb, c1 + bb);
                }
            }
        }
}

// ---------------- depthwise conv body (predicated, small taps) ----------
template <int KS, int DIL, int PAD>
__device__ __forceinline__ void dw_conv_tile(const float* __restrict__ tile,
                                             const float* __restrict__ w,
                                             float* gout) {
    for (int p = threadIdx.x; p < PP; p += 256) {
        int h = p >> 6, ww = p & 63;
        float s = 0.f;
#pragma unroll
        for (int kh = 0; kh < KS; kh++) {
            int hh = h + DIL * kh - PAD;
            if ((unsigned)hh >= (unsigned)HH) continue;
#pragma unroll
            for (int kw = 0; kw < KS; kw++) {
                int wc = ww + DIL * kw - PAD;
                if ((unsigned)wc >= (unsigned)WW) continue;
                s += tile[hh * WW + wc] * w[kh * KS + kw];
            }
        }
        gout[p] = s;
    }
}

// two independent 3x3 depthwise convs in one launch (unpadded, proven)
__global__ void __launch_bounds__(256) dw3x3_pair(const float* __restrict__ X0,
                                                  const float* __restrict__ W0,
                                                  float* __restrict__ Y0,
                                                  const float* __restrict__ X1,
                                                  const float* __restrict__ W1,
                                                  float* __restrict__ Y1) {
    __shared__ float tile[PP];
    __shared__ float w[9];
    int id = blockIdx.x;
    int which = id >> 9, bc = id & 511;
    int c = bc & (CC - 1);
    const float* X = which ? X1 : X0;
    const float* Wd = which ? W1 : W0;
    float* Y = which ? Y1 : Y0;
    const float4* xp = (const float4*)(X + (size_t)bc * PP);
    for (int p = threadIdx.x; p < PP / 4; p += 256)
        ((float4*)tile)[p] = xp[p];
    if (threadIdx.x < 9) w[threadIdx.x] = Wd[c * 9 + threadIdx.x];
    __syncthreads();
    dw_conv_tile<3, 1, 1>(tile, w, Y + (size_t)bc * PP);
}

// fused LKA depthwise chain with padded tiles (proven)
__global__ void __launch_bounds__(256) lka_chain(const float* __restrict__ X,
                                                 const float* __restrict__ W5,
                                                 const float* __restrict__ W7,
                                                 float* __restrict__ OUT) {
    __shared__ float t0p[68 * 68];
    __shared__ float t1p[82 * 84];
    __shared__ float w5[25], w7[49];
    int bc = blockIdx.x;
    int c = bc & (CC - 1);
    for (int i = threadIdx.x; i < (68 * 68) / 4; i += 256)
        ((float4*)t0p)[i] = make_float4(0.f, 0.f, 0.f, 0.f);
    for (int i = threadIdx.x; i < (82 * 84) / 4; i += 256)
        ((float4*)t1p)[i] = make_float4(0.f, 0.f, 0.f, 0.f);
    if (threadIdx.x < 25) w5[threadIdx.x] = W5[c * 25 + threadIdx.x];
    else if (threadIdx.x >= 32 && threadIdx.x < 81)
        w7[threadIdx.x - 32] = W7[c * 49 + threadIdx.x - 32];
    __syncthreads();
    const float* xp = X + (size_t)bc * PP;
    for (int p = threadIdx.x; p < PP; p += 256) {
        int h = p >> 6, ww = p & 63;
        t0p[(h + 2) * 68 + ww + 2] = xp[p];
    }
    __syncthreads();
    for (int p = threadIdx.x; p < PP; p += 256) {
        int h = p >> 6, ww = p & 63;
        const float* base = &t0p[h * 68 + ww];
        float s = 0.f;
#pragma unroll
        for (int kh = 0; kh < 5; kh++)
#pragma unroll
            for (int kw = 0; kw < 5; kw++)
                s += base[kh * 68 + kw] * w5[kh * 5 + kw];
        t1p[(h + 9) * 84 + ww + 9] = s;
    }
    __syncthreads();
    float* yp = OUT + (size_t)bc * PP;
    for (int p = threadIdx.x; p < PP; p += 256) {
        int h = p >> 6, ww = p & 63;
        const float* base = &t1p[h * 84 + ww];
        float s = 0.f;
#pragma unroll
        for (int kh = 0; kh < 7; kh++)
#pragma unroll
            for (int kw = 0; kw < 7; kw++)
                s += base[kh * 3 * 84 + kw * 3] * w7[kh * 7 + kw];
        yp[p] = s;
    }
}

// ---------------- c2a grouped conv (groups=32) + SimpleGate ----------------
__global__ void __launch_bounds__(256) c2a_gate(const float* __restrict__ X,
                                                const float* __restrict__ Wg,
                                                const float* __restrict__ bg,
                                                float* __restrict__ TG) {
    int b = blockIdx.x >> 4, j = blockIdx.x & 15;
    int p0 = blockIdx.y * 512;
    __shared__ float w1[72], w2[72];
    if (threadIdx.x < 72) w1[threadIdx.x] = Wg[j * 72 + threadIdx.x];
    else if (threadIdx.x < 144) w2[threadIdx.x - 72] = Wg[(16 + j) * 72 + threadIdx.x - 72];
    __syncthreads();
    float b1 = bg[j], b2 = bg[16 + j];
    const float* x1p = X + ((size_t)b * CC + j * 8) * PP;
    const float* x2p = X + ((size_t)b * CC + (16 + j) * 8) * PP;
    for (int p = p0 + threadIdx.x; p < p0 + 512; p += 256) {
        int h = p >> 6, wq = p & 63;
        float t1 = b1, t2 = b2;
        for (int ci = 0; ci < 8; ci++) {
#pragma unroll
            for (int kh = 0; kh < 3; kh++) {
                int hh = h + kh - 1;
                if ((unsigned)hh >= (unsigned)HH) continue;
#pragma unroll
                for (int kw = 0; kw < 3; kw++) {
                    int wc = wq + kw - 1;
                    if ((unsigned)wc >= (unsigned)WW) continue;
                    float xv1 = x1p[(size_t)ci * PP + hh * WW + wc];
                    float xv2 = x2p[(size_t)ci * PP + hh * WW + wc];
                    t1 += xv1 * w1[ci * 9 + kh * 3 + kw];
                    t2 += xv2 * w2[ci * 9 + kh * 3 + kw];
                }
            }
        }
        TG[((size_t)b * 16 + j) * PP + p] = t1 * t2;
    }
}

// ---------------- att pair -> packed bf16x2 [b][kp][pix] ----------------
__global__ void __launch_bounds__(256) att_mix_pk(const float* __restrict__ TG,
                                                  const float* __restrict__ c2bw,
                                                  const float* __restrict__ c2bb,
                                                  const float* __restrict__ attg,
                                                  const float* __restrict__ ATTLIN,
                                                  uint32_t* __restrict__ APK) {
    int kp = blockIdx.x;                 // 0..63
    int b = blockIdx.z;
    int p0 = blockIdx.y * 1024;
    int n0 = 2 * kp, n1 = n0 + 1;
    float wr0[16], wr1[16];
#pragma unroll
    for (int q = 0; q < 16; q++) {
        wr0[q] = c2bw[n0 * 16 + q];
        wr1[q] = c2bw[n1 * 16 + q];
    }
    float bb0 = c2bb[n0], gam0 = attg[n0];
    float bb1 = c2bb[n1], gam1 = attg[n1];
    const float* tgb = TG + (size_t)b * 16 * PP;
    const float* al0 = ATTLIN + ((size_t)b * NSET + n0) * PP;
    const float* al1 = ATTLIN + ((size_t)b * NSET + n1) * PP;
    uint32_t* dst = APK + ((size_t)b * 64 + kp) * PP;
    for (int p = p0 + threadIdx.x; p < p0 + 1024; p += 256) {
        float s0 = bb0, s1 = bb1;
#pragma unroll
        for (int q = 0; q < 16; q++) {
            float t = tgb[(size_t)q * PP + p];
            s0 += t * wr0[q];
            s1 += t * wr1[q];
        }
        dst[p] = pack_bf16n(s0 * gam0 + al0[p], s1 * gam1 + al1[p]);
    }
}

// =========================================================================
// Dual-pass IKBA, bf16 k16 mma, prepacked operands (R15-proven).
// =========================================================================
#define A_ST 136
#define BKP_ST 36
#define IK_BV (32 * A_ST)                  // 4352
#define IK_BH (IK_BV + 56 * BKP_ST)        // 6368
#define IKBA_SMEM_FLOATS 15104

__global__ void __launch_bounds__(128, 3) ikba_dual(
        const uint32_t* __restrict__ APK, const uint32_t* __restrict__ WPK,
        const float* __restrict__ bcb, const float* __restrict__ ga1,
        const float* __restrict__ UF, float* __restrict__ OUT) {
    extern __shared__ float sm[];
    uint32_t* Ap = (uint32_t*)sm;              // [32 kp][A_ST]
    uint32_t* BV = (uint32_t*)(sm + IK_BV);    // [56 n][BKP_ST]
    uint32_t* BH = (uint32_t*)(sm + IK_BH);    // [56 n][BKP_ST]
    float* CsV = sm;                           // alias: [128][57]
    float* CsH = sm + 7296;                    // alias: [128][57]
    float* xh = sm + 14592;                    // alias: [4][128]

    int gr = blockIdx.x, h2 = blockIdx.y, b = blockIdx.z;
    int tid = threadIdx.x;
    int warp = tid >> 5, lane = tid & 31;
    int qr = lane >> 2, l4 = lane & 3;
    int m_base = warp << 5;

    float accV[2][7][4], accH[2][7][4];
#pragma unroll
    for (int i = 0; i < 2; i++)
#pragma unroll
        for (int j = 0; j < 7; j++)
#pragma unroll
            for (int t = 0; t < 4; t++) { accV[i][j][t] = 0.f; accH[i][j][t] = 0.f; }

#pragma unroll
    for (int kc = 0; kc < 2; kc++) {
        {
            int quad = tid & 31, klane = tid >> 5;
            const uint32_t* apk = APK + ((size_t)b * 64 + kc * 32) * PP
                                + (size_t)h2 * 128 + quad * 4;
#pragma unroll
            for (int kk = 0; kk < 32; kk += 4) {
                int kp = kk + klane;
                *(uint4*)&Ap[kp * A_ST + quad * 4] =
                    *(const uint4*)&apk[(size_t)kp * PP];
            }
        }
        {
            const uint32_t* wv = WPK + (size_t)(gr * 48) * 64 + kc * 32;
            const uint32_t* wh = WPK + (size_t)(3072 + gr * 48) * 64 + kc * 32;
#pragma unroll
            for (int j = 0; j < 3; j++) {
                int l = j * 128 + tid;
                int n = l >> 3, q = l & 7;
                *(uint4*)&BV[n * BKP_ST + q * 4] =
                    *(const uint4*)&wv[(size_t)n * 64 + q * 4];
                *(uint4*)&BH[n * BKP_ST + q * 4] =
                    *(const uint4*)&wh[(size_t)n * 64 + q * 4];
            }
        }
        int kbase = kc * 64;
#pragma unroll
        for (int j = 0; j < 2; j++) {
            int l = j * 128 + tid;
            int kp = l >> 3, n = 48 + (l & 7);
            BV[n * BKP_ST + kp] = 0u;
            float v0 = 0.f, v1 = 0.f;
            if (n < 52) {
                v0 = bcb[(kbase + 2 * kp) * CC + gr * CGC + (n - 48)];
                v1 = bcb[(kbase + 2 * kp + 1) * CC + gr * CGC + (n - 48)];
            }
            BH[n * BKP_ST + kp] = pack_bf16n(v0, v1);
        }
        __syncthreads();

        for (int kq = 0; kq < 32; kq += 8) {
            uint32_t a[2][4];
            int ka = (kq + l4) * A_ST;
            int ka2 = (kq + 4 + l4) * A_ST;
#pragma unroll
            for (int mt = 0; mt < 2; mt++) {
                int row = m_base + mt * 16 + qr;
                a[mt][0] = Ap[ka + row];
                a[mt][1] = Ap[ka + row + 8];
                a[mt][2] = Ap[ka2 + row];
                a[mt][3] = Ap[ka2 + row + 8];
            }
#pragma unroll
            for (int nt = 0; nt < 7; nt++) {
                int nr = (nt * 8 + qr) * BKP_ST + kq + l4;
                uint32_t bv0 = BV[nr], bv1 = BV[nr + 4];
                uint32_t bh0 = BH[nr], bh1 = BH[nr + 4];
#pragma unroll
                for (int mt = 0; mt < 2; mt++) {
                    MMA_BF16(accV[mt][nt], a[mt], bv0, bv1);
                    MMA_BF16(accH[mt][nt], a[mt], bh0, bh1);
                }
            }
        }
        __syncthreads();
    }

#pragma unroll
    for (int mt = 0; mt < 2; mt++)
#pragma unroll
        for (int nt = 0; nt < 7; nt++) {
            int r = m_base + mt * 16 + qr;
            int cl = nt * 8 + 2 * l4;
            CsV[r * 57 + cl]           = accV[mt][nt][0];
            CsV[r * 57 + cl + 1]       = accV[mt][nt][1];
            CsV[(r + 8) * 57 + cl]     = accV[mt][nt][2];
            CsV[(r + 8) * 57 + cl + 1] = accV[mt][nt][3];
            CsH[r * 57 + cl]           = accH[mt][nt][0];
            CsH[r * 57 + cl + 1]       = accH[mt][nt][1];
            CsH[(r + 8) * 57 + cl]     = accH[mt][nt][2];
            CsH[(r + 8) * 57 + cl + 1] = accH[mt][nt][3];
        }
    __syncthreads();

    int pix = tid, r0 = pix >> 6, cp = pix & 63;
    int h = h2 * 2 + r0;
    {
        float uf[12];
        size_t srcBase = (size_t)(b * CC + gr * CGC) * PP;
#pragma unroll
        for (int ci = 0; ci < 4; ci++)
#pragma unroll
            for (int tap = 0; tap < 3; tap++) {
                float v = 0.f;
                int hh = h + tap - 1;
                if ((unsigned)hh < (unsigned)HH)
                    v = UF[srcBase + (size_t)ci * PP + hh * WW + cp];
                uf[ci * 3 + tap] = v;
            }
        const float* cpr = &CsV[pix * 57];
#pragma unroll
        for (int oi = 0; oi < 4; oi++) {
            float s = 0.f;
#pragma unroll
            for (int j = 0; j < 12; j++) s += cpr[oi * 12 + j] * uf[j];
            xh[oi * 128 + pix] = s;
        }
    }
    __syncthreads();

    {
        float ufh[12];
#pragma unroll
        for (int ci = 0; ci < 4; ci++)
#pragma unroll
            for (int tap = 0; tap < 3; tap++) {
                float v = 0.f;
                int wc = cp + tap - 1;
                if ((unsigned)wc < (unsigned)WW)
                    v = xh[ci * 128 + pix + tap - 1];
                ufh[ci * 3 + tap] = v;
            }
        const float* cpr = &CsH[pix * 57];
        size_t obase = (size_t)(b * CC + gr * CGC) * PP + (size_t)h2 * 128 + pix;
#pragma unroll
        for (int oi = 0; oi < 4; oi++) {
            float s = cpr[48 + oi];
#pragma unroll
            for (int j = 0; j < 12; j++) s += cpr[oi * 12 + j] * ufh[j];
            size_t oidx = obase + (size_t)oi * PP;
            OUT[oidx] = s * ga1[gr * CGC + oi] + UF[oidx];
        }
    }
}

// ---------------- launch ----------------
extern "C" void kernel_launch(void* const* d_in, const int* in_sizes, int n_in,
                              void* d_out, int out_size) {
    const float* x       = (const float*)d_in[0];
    const float* dw1_w   = (const float*)d_in[1];
    const float* dw2_w   = (const float*)d_in[2];
    const float* proj_w  = (const float*)d_in[3];
    const float* lka0_w  = (const float*)d_in[4];
    const float* lkas_w  = (const float*)d_in[5];
    const float* lka1_w  = (const float*)d_in[6];
    const float* lka1_b  = (const float*)d_in[7];
    const float* sca_w   = (const float*)d_in[8];
    const float* sca_b   = (const float*)d_in[9];
    const float* c1a_w   = (const float*)d_in[10];
    const float* c1b_w   = (const float*)d_in[11];
    const float* c2a_w   = (const float*)d_in[12];
    const float* c2a_b   = (const float*)d_in[13];
    const float* c2b_w   = (const float*)d_in[14];
    const float* c2b_b   = (const float*)d_in[15];
    const float* c211_w  = (const float*)d_in[16];
    const float* c211_b  = (const float*)d_in[17];
    const float* w_cb    = (const float*)d_in[18];
    const float* b_cb    = (const float*)d_in[19];
    const float* attgam  = (const float*)d_in[20];
    const float* ga1     = (const float*)d_in[21];
    float* out = (float*)d_out;

    float *meanb, *scab, *ydw1, *yc1a, *attlin, *x1b, *ufb, *l1,
          *tg, *x2b, *zb;
    uint32_t *attpk, *wpk;
    cudaGetSymbolAddress((void**)&meanb, g_mean);
    cudaGetSymbolAddress((void**)&scab, g_sca);
    cudaGetSymbolAddress((void**)&ydw1, g_ydw1);
    cudaGetSymbolAddress((void**)&yc1a, g_yc1a);
    cudaGetSymbolAddress((void**)&attlin, g_attlin);
    cudaGetSymbolAddress((void**)&x1b, g_x1);
    cudaGetSymbolAddress((void**)&ufb, g_uf);
    cudaGetSymbolAddress((void**)&l1, g_l1);
    cudaGetSymbolAddress((void**)&tg, g_tg);
    cudaGetSymbolAddress((void**)&attpk, g_attpk);
    cudaGetSymbolAddress((void**)&wpk, g_wpk);
    cudaGetSymbolAddress((void**)&x2b, g_x2);
    cudaGetSymbolAddress((void**)&zb, g_z);

    size_t gt_smem = GT_SMEM_FLOATS * sizeof(float);

    // prep: pack wcb to bf16 pairs
    wcb_pack<<<24, 256>>>(w_cb, wpk);

    // channel-attention branch (fast warp-per-output sca)
    meankern<<<BB * CC, 256>>>(x, meanb);
    scakern<<<64, 256>>>(meanb, sca_w, sca_b, scab);

    // 1x1 convs from x, batched (dw1 -> ydw1, c1a -> yc1a, c211 -> attlin)
    gemm_tc<0><<<dim3(32, 10, BB), 256, gt_smem>>>(
        dw1_w, c1a_w, c211_w, c211_b, x, ydw1, yc1a, attlin,
        nullptr, nullptr, nullptr);

    // depthwise: two 3x3 merged (unpadded); LKA chain (padded tiles)
    dw3x3_pair<<<BB * CC * 2, 256>>>(ydw1, dw2_w, x1b, yc1a, c1b_w, ufb);
    lka_chain<<<BB * CC, 256>>>(x, lka0_w, lkas_w, l1);

    // attention map -> packed bf16
    c2a_gate<<<dim3(BB * 16, 8), 256>>>(x, c2a_w, c2a_b, tg);
    att_mix_pk<<<dim3(64, 4, BB), 256>>>(tg, c2b_w, c2b_b, attgam, attlin, attpk);

    // dual-pass IKBA (bf16 k16 mma, prepacked fills)
    size_t shmem = IKBA_SMEM_FLOATS * sizeof(float);
    cudaFuncSetAttribute(ikba_dual, cudaFuncAttributeMaxDynamicSharedMemorySize,
                         (int)shmem);
    ikba_dual<<<dim3(GG, 32, BB), 128, shmem>>>(attpk, wpk, b_cb, ga1, ufb, x2b);

    // lka1 GEMM with fused elementwise merge: z = (W@l1+b)*x1*x2*sca
    gemm_tc<1><<<dim3(32, 4, BB), 256, gt_smem>>>(
        lka1_w, nullptr, nullptr, lka1_b, l1, zb, nullptr, nullptr,
        x1b, x2b, scab);

    // final projection
    gemm_tc<2><<<dim3(32, 4, BB), 256, gt_smem>>>(
        proj_w, nullptr, nullptr, nullptr, zb, out, nullptr, nullptr,
        nullptr, nullptr, nullptr);
}